// round 2
// baseline (speedup 1.0000x reference)
#include <cuda_runtime.h>
#include <cuda_fp16.h>

#define HID   2048
#define FH    8192   // 4*H
#define TLEN  8192
#define NCTA  128
#define TPB   512
#define JPC   16     // h-lanes per CTA (2048/128)
#define ROWS  64     // gate rows per CTA (4*JPC)
#define SMEM_W_ROWS 48  // 48 rows in smem, 16 rows (1/warp) in registers

// SMEM: 48 rows * 2048 halves * 2B = 196608, plus fp32 region:
// hs(2048) + gates(64) + c(16) + wih(192) + b(64) + x(4) = 2388 floats = 9552 B
#define SMEM_BYTES (SMEM_W_ROWS*HID*2 + (HID + ROWS + JPC + ROWS*3 + ROWS + 4)*4)

// ---- device scratch (static allocation only; no cudaMalloc allowed) ----
__device__ __align__(16) __half g_Whh[(size_t)FH * HID];   // 32 MB fp16 weights
__device__ __align__(16) float  g_h[2 * HID];              // double-buffered hidden state
__device__ __align__(16) float  g_feat[4 * HID];
__device__ __align__(16) float  g_hid[HID];
__device__ int g_bar;

__global__ void prep_kernel(const float* __restrict__ Whh) {
    size_t idx = (size_t)blockIdx.x * blockDim.x + threadIdx.x;
    size_t stride = (size_t)gridDim.x * blockDim.x;
    const size_t total = (size_t)FH * HID;
    for (size_t i = idx; i < total; i += stride)
        g_Whh[i] = __float2half(Whh[i]);
    if (idx < 2 * HID) g_h[idx] = 0.f;
    if (idx == 0) g_bar = 0;
}

__device__ __forceinline__ float sigf(float v) { return 1.f / (1.f + expf(-v)); }

__global__ void __launch_bounds__(TPB, 1) lstm_kernel(
    const float* __restrict__ x,
    const float* __restrict__ last_dist,
    const float* __restrict__ last_heading,
    const float* __restrict__ Wih,
    const float* __restrict__ bih,
    const float* __restrict__ bhh)
{
    extern __shared__ char sm_raw[];
    __half* ws   = (__half*)sm_raw;                                  // [48][2048]
    float* hs    = (float*)(sm_raw + SMEM_W_ROWS * HID * 2);         // [2048]
    float* gsm   = hs + HID;                                         // [64]
    float* cbuf  = gsm + ROWS;                                       // [16]
    float* wih_s = cbuf + JPC;                                       // [64][3]
    float* bsm   = wih_s + ROWS * 3;                                 // [64]
    float* xs    = bsm + ROWS;                                       // [4]

    const int tid = threadIdx.x;
    const int w   = tid >> 5;
    const int l   = tid & 31;
    const int blk = blockIdx.x;

    // ---- init: stage weights. Local row r (0..63): gate = r>>4, jl = r&15,
    // global row = gate*2048 + blk*16 + jl. Warp w owns rows {w, w+16, w+32, w+48};
    // row w lives in registers, the other 3 in smem. ----
    uint2 wreg[16];
    {
        int r = w;
        size_t grow = (size_t)(r >> 4) * HID + (size_t)blk * JPC + (r & 15);
        const uint2* gp = (const uint2*)(g_Whh + grow * HID);
        #pragma unroll
        for (int i = 0; i < 16; i++) wreg[i] = gp[l + 32 * i];
    }
    #pragma unroll
    for (int s = 1; s < 4; s++) {
        int r = w + 16 * s;
        size_t grow = (size_t)(r >> 4) * HID + (size_t)blk * JPC + (r & 15);
        const uint2* gp = (const uint2*)(g_Whh + grow * HID);
        uint2* sp = (uint2*)(ws + (size_t)(r - 16) * HID);
        #pragma unroll
        for (int i = 0; i < 16; i++) sp[l + 32 * i] = gp[l + 32 * i];
    }
    if (tid < ROWS * 3) {
        int r = tid / 3, c = tid - 3 * r;
        size_t grow = (size_t)(r >> 4) * HID + (size_t)blk * JPC + (r & 15);
        wih_s[tid] = Wih[grow * 3 + c];
    }
    if (tid < ROWS) {
        size_t grow = (size_t)(tid >> 4) * HID + (size_t)blk * JPC + (tid & 15);
        bsm[tid] = bih[grow] + bhh[grow];
    }
    if (tid < JPC) cbuf[tid] = 0.f;
    ((float4*)hs)[tid] = make_float4(0.f, 0.f, 0.f, 0.f);   // h0 = 0
    if (tid < 3) xs[tid] = x[tid];
    __syncthreads();

    for (int t = 0; t <= TLEN; t++) {
        // 1. snapshot h into registers: lane l owns k = 4l + 128i, i=0..15
        float4 h4[16];
        const float4* hs4 = (const float4*)hs;
        #pragma unroll
        for (int i = 0; i < 16; i++) h4[i] = hs4[l + 32 * i];

        // 2. four dot products (one per gate) per warp
        float acc_out[4];
        #pragma unroll
        for (int s = 0; s < 4; s++) {
            float a0 = 0.f, a1 = 0.f;
            if (s == 0) {
                #pragma unroll
                for (int i = 0; i < 16; i++) {
                    uint2 u = wreg[i];
                    float2 f0 = __half22float2(*(__half2*)&u.x);
                    float2 f1 = __half22float2(*(__half2*)&u.y);
                    float4 hv = h4[i];
                    a0 = fmaf(f0.x, hv.x, a0);
                    a1 = fmaf(f0.y, hv.y, a1);
                    a0 = fmaf(f1.x, hv.z, a0);
                    a1 = fmaf(f1.y, hv.w, a1);
                }
            } else {
                const uint2* wp = (const uint2*)(ws + (size_t)(w + 16 * s - 16) * HID);
                #pragma unroll
                for (int i = 0; i < 16; i++) {
                    uint2 u = wp[l + 32 * i];
                    float2 f0 = __half22float2(*(__half2*)&u.x);
                    float2 f1 = __half22float2(*(__half2*)&u.y);
                    float4 hv = h4[i];
                    a0 = fmaf(f0.x, hv.x, a0);
                    a1 = fmaf(f0.y, hv.y, a1);
                    a0 = fmaf(f1.x, hv.z, a0);
                    a1 = fmaf(f1.y, hv.w, a1);
                }
            }
            float a = a0 + a1;
            #pragma unroll
            for (int off = 16; off > 0; off >>= 1)
                a += __shfl_xor_sync(0xffffffffu, a, off);
            acc_out[s] = a;
        }
        if (l == 0) {
            #pragma unroll
            for (int s = 0; s < 4; s++) {
                int r = w + 16 * s;
                float g = acc_out[s] + bsm[r];
                if (t < TLEN)
                    g += wih_s[r * 3] * xs[0] + wih_s[r * 3 + 1] * xs[1] + wih_s[r * 3 + 2] * xs[2];
                gsm[r] = g;
            }
        }
        __syncthreads();

        if (t < TLEN) {
            // 3. cell update for this CTA's 16 lanes; h_{t+1} -> buffer (t+1)&1
            if (tid < JPC) {
                float gi = gsm[tid], gf = gsm[16 + tid], gg = gsm[32 + tid], go = gsm[48 + tid];
                float c = sigf(gf) * cbuf[tid] + sigf(gi) * tanhf(gg);
                cbuf[tid] = c;
                g_h[((t + 1) & 1) * HID + blk * JPC + tid] = sigf(go) * tanhf(c);
            }
            // 4. chip-wide barrier (all 128 CTAs resident, 1/SM: safe spin)
            __threadfence();
            __syncthreads();
            if (tid == 0) {
                atomicAdd(&g_bar, 1);
                int tgt = NCTA * (t + 1);
                while (*(volatile int*)&g_bar < tgt) { }
            }
            __syncthreads();
            // 5. refill smem h from the buffer just written; prefetch x[t+1]
            float4 hv = __ldcg(((const float4*)(g_h + ((t + 1) & 1) * HID)) + tid);
            ((float4*)hs)[tid] = hv;
            if (t + 1 < TLEN && tid < 3) xs[tid] = x[(t + 1) * 3 + tid];
            __syncthreads();
        } else {
            // final iteration (t == TLEN): dots used hn; 4 action rollouts share
            // the W_hh @ hn term, differ only in the 3-dim W_ih contribution.
            if (tid < JPC) {
                float ld = *last_dist, lh = *last_heading;
                float c0 = cbuf[tid];
                float gi0 = gsm[tid], gf0 = gsm[16 + tid], gg0 = gsm[32 + tid], go0 = gsm[48 + tid];
                int r0 = tid, r1 = 16 + tid, r2 = 32 + tid, r3 = 48 + tid;
                #pragma unroll
                for (int a = 0; a < 4; a++) {
                    float af = (float)a;
                    float gi = gi0 + wih_s[r0 * 3] * ld + wih_s[r0 * 3 + 1] * lh + wih_s[r0 * 3 + 2] * af;
                    float gf = gf0 + wih_s[r1 * 3] * ld + wih_s[r1 * 3 + 1] * lh + wih_s[r1 * 3 + 2] * af;
                    float gg = gg0 + wih_s[r2 * 3] * ld + wih_s[r2 * 3 + 1] * lh + wih_s[r2 * 3 + 2] * af;
                    float go = go0 + wih_s[r3 * 3] * ld + wih_s[r3 * 3 + 1] * lh + wih_s[r3 * 3 + 2] * af;
                    float c = sigf(gf) * c0 + sigf(gi) * tanhf(gg);
                    g_feat[a * HID + blk * JPC + tid] = sigf(go) * tanhf(c);
                }
            }
        }
    }
}

// hid = relu(W1 @ feat + b1): 2048 rows x 8192. One warp per row, HBM-bound (~8us).
__global__ void mlp1_kernel(const float* __restrict__ W1, const float* __restrict__ b1) {
    int w = threadIdx.x >> 5, l = threadIdx.x & 31;
    int row = blockIdx.x * 8 + w;
    const float4* wp = (const float4*)(W1 + (size_t)row * FH);
    const float4* fp = (const float4*)g_feat;
    float a0 = 0.f, a1 = 0.f, a2 = 0.f, a3 = 0.f;
    #pragma unroll 8
    for (int i = 0; i < 64; i++) {
        float4 wv = wp[l + 32 * i];
        float4 fv = fp[l + 32 * i];
        a0 = fmaf(wv.x, fv.x, a0);
        a1 = fmaf(wv.y, fv.y, a1);
        a2 = fmaf(wv.z, fv.z, a2);
        a3 = fmaf(wv.w, fv.w, a3);
    }
    float a = (a0 + a1) + (a2 + a3);
    #pragma unroll
    for (int off = 16; off > 0; off >>= 1) a += __shfl_xor_sync(0xffffffffu, a, off);
    if (l == 0) g_hid[row] = fmaxf(a + b1[row], 0.f);
}

// out = W2 @ hid + b2: 4 rows x 2048, one warp each.
__global__ void mlp2_kernel(const float* __restrict__ W2, const float* __restrict__ b2,
                            float* __restrict__ out) {
    int w = threadIdx.x >> 5, l = threadIdx.x & 31;
    const float4* wp = (const float4*)(W2 + (size_t)w * HID);
    const float4* hp = (const float4*)g_hid;
    float a0 = 0.f, a1 = 0.f, a2 = 0.f, a3 = 0.f;
    #pragma unroll
    for (int i = 0; i < 16; i++) {
        float4 wv = wp[l + 32 * i];
        float4 hv = hp[l + 32 * i];
        a0 = fmaf(wv.x, hv.x, a0);
        a1 = fmaf(wv.y, hv.y, a1);
        a2 = fmaf(wv.z, hv.z, a2);
        a3 = fmaf(wv.w, hv.w, a3);
    }
    float a = (a0 + a1) + (a2 + a3);
    #pragma unroll
    for (int off = 16; off > 0; off >>= 1) a += __shfl_xor_sync(0xffffffffu, a, off);
    if (l == 0) out[w] = a + b2[w];
}

extern "C" void kernel_launch(void* const* d_in, const int* in_sizes, int n_in,
                              void* d_out, int out_size) {
    const float* x   = (const float*)d_in[0];
    const float* ld  = (const float*)d_in[1];
    const float* lh  = (const float*)d_in[2];
    const float* Wih = (const float*)d_in[3];
    const float* Whh = (const float*)d_in[4];
    const float* bih = (const float*)d_in[5];
    const float* bhh = (const float*)d_in[6];
    const float* W1  = (const float*)d_in[7];
    const float* b1  = (const float*)d_in[8];
    const float* W2  = (const float*)d_in[9];
    const float* b2  = (const float*)d_in[10];
    float* out = (float*)d_out;

    cudaFuncSetAttribute(lstm_kernel, cudaFuncAttributeMaxDynamicSharedMemorySize, SMEM_BYTES);

    prep_kernel<<<2048, 256>>>(Whh);
    lstm_kernel<<<NCTA, TPB, SMEM_BYTES>>>(x, ld, lh, Wih, bih, bhh);
    mlp1_kernel<<<HID / 8, 256>>>(W1, b1);
    mlp2_kernel<<<1, 128>>>(W2, b2, out);
}